// round 14
// baseline (speedup 1.0000x reference)
#include <cuda_runtime.h>
#include <cuda_bf16.h>
#include <math.h>
#include <cstdint>

// DeepseekV3 MLA attention forward.
// GEMMs + flash attention on mma.sync bf16 with hi+lo split precision.
// R14: GEMM tiles 256(M)x128(N), 256 thr, warp tile 64x64 — halves bytes/MMA
// without hitting the 128-reg/thread wall a 512-thread CTA would impose.

#define B_   2
#define T_   2048
#define HID_ 2048
#define NH_  16
#define QLR_ 1536
#define KVLR_ 512
#define DN_  128
#define DR_  64
#define DQK_ 192
#define DV_  128
#define ROWS_ (B_*T_)           // 4096
#define QW_  (NH_*DQK_)         // 3072
#define KVW_ (NH_*(DN_+DV_))    // 4096
#define CKVW_ (KVLR_+DR_)       // 576
#define QAW_ (QLR_+CKVW_)       // 2112

// ------------------------- scratch (device globals) -------------------------
__device__ float g_qa2 [(size_t)ROWS_*QAW_];   // [qa(1536) | ckv(576)]
__device__ float g_qrot[(size_t)B_*NH_*T_*DR_]; // un-roped q rot dims

// bf16 split activations
__device__ __nv_bfloat16 g_x_h  [(size_t)ROWS_*HID_];
__device__ __nv_bfloat16 g_x_l  [(size_t)ROWS_*HID_];
__device__ __nv_bfloat16 g_qan_h[(size_t)ROWS_*QLR_];
__device__ __nv_bfloat16 g_qan_l[(size_t)ROWS_*QLR_];
__device__ __nv_bfloat16 g_kvn_h[(size_t)ROWS_*KVLR_];
__device__ __nv_bfloat16 g_kvn_l[(size_t)ROWS_*KVLR_];
__device__ __nv_bfloat16 g_att_h[(size_t)ROWS_*(NH_*DV_)];
__device__ __nv_bfloat16 g_att_l[(size_t)ROWS_*(NH_*DV_)];

// per-head split Q/K/V for attention ([bh][t][d])
__device__ __nv_bfloat16 g_Qh[(size_t)B_*NH_*T_*DQK_];
__device__ __nv_bfloat16 g_Ql[(size_t)B_*NH_*T_*DQK_];
__device__ __nv_bfloat16 g_Kh[(size_t)B_*NH_*T_*DQK_];
__device__ __nv_bfloat16 g_Kl[(size_t)B_*NH_*T_*DQK_];
__device__ __nv_bfloat16 g_Vh[(size_t)B_*NH_*T_*DV_];
__device__ __nv_bfloat16 g_Vl[(size_t)B_*NH_*T_*DV_];

// bf16 split transposed weights [N,K]
__device__ __nv_bfloat16 g_wqkva_h[(size_t)QAW_*HID_];
__device__ __nv_bfloat16 g_wqkva_l[(size_t)QAW_*HID_];
__device__ __nv_bfloat16 g_wqb_h [(size_t)QW_*QLR_];
__device__ __nv_bfloat16 g_wqb_l [(size_t)QW_*QLR_];
__device__ __nv_bfloat16 g_wkvb_h[(size_t)KVW_*KVLR_];
__device__ __nv_bfloat16 g_wkvb_l[(size_t)KVW_*KVLR_];
__device__ __nv_bfloat16 g_wo_h  [(size_t)HID_*(NH_*DV_)];
__device__ __nv_bfloat16 g_wo_l  [(size_t)HID_*(NH_*DV_)];

// ------------------------------ PTX helpers ---------------------------------
__device__ __forceinline__ uint32_t smem_u32(const void* p) {
    uint32_t a;
    asm("{ .reg .u64 t; cvta.to.shared.u64 t, %1; cvt.u32.u64 %0, t; }"
        : "=r"(a) : "l"(p));
    return a;
}
__device__ __forceinline__ void cp16(uint32_t s, const void* g, bool ok) {
    asm volatile("cp.async.cg.shared.global [%0], [%1], 16, %2;"
        :: "r"(s), "l"(g), "r"(ok ? 16 : 0));
}
#define CP_COMMIT() asm volatile("cp.async.commit_group;" ::: "memory")
#define CP_WAIT(n)  asm volatile("cp.async.wait_group %0;" :: "n"(n) : "memory")

__device__ __forceinline__ void ldm_x4(uint32_t* r, uint32_t addr) {
    asm volatile("ldmatrix.sync.aligned.m8n8.x4.shared.b16 {%0,%1,%2,%3}, [%4];"
        : "=r"(r[0]), "=r"(r[1]), "=r"(r[2]), "=r"(r[3]) : "r"(addr));
}
__device__ __forceinline__ void ldm_x4_t(uint32_t* r, uint32_t addr) {
    asm volatile("ldmatrix.sync.aligned.m8n8.x4.trans.shared.b16 {%0,%1,%2,%3}, [%4];"
        : "=r"(r[0]), "=r"(r[1]), "=r"(r[2]), "=r"(r[3]) : "r"(addr));
}
__device__ __forceinline__ void mma16816(float* d, const uint32_t* a, const uint32_t* b) {
    asm volatile(
        "mma.sync.aligned.m16n8k16.row.col.f32.bf16.bf16.f32 "
        "{%0,%1,%2,%3}, {%4,%5,%6,%7}, {%8,%9}, {%0,%1,%2,%3};"
        : "+f"(d[0]), "+f"(d[1]), "+f"(d[2]), "+f"(d[3])
        : "r"(a[0]), "r"(a[1]), "r"(a[2]), "r"(a[3]), "r"(b[0]), "r"(b[1]));
}
__device__ __forceinline__ void split_bf16(float v, __nv_bfloat16& h, __nv_bfloat16& l) {
    h = __float2bfloat16_rn(v);
    l = __float2bfloat16_rn(v - __bfloat162float(h));
}
__device__ __forceinline__ __nv_bfloat162 split2_h(float a, float b) {
    return __nv_bfloat162(__float2bfloat16_rn(a), __float2bfloat16_rn(b));
}
__device__ __forceinline__ __nv_bfloat162 split2_l(float a, float b) {
    __nv_bfloat16 ha = __float2bfloat16_rn(a), hb = __float2bfloat16_rn(b);
    return __nv_bfloat162(__float2bfloat16_rn(a - __bfloat162float(ha)),
                          __float2bfloat16_rn(b - __bfloat162float(hb)));
}

// ---------------- split-bf16 GEMM: C = A @ B^T, mma.sync ---------------------
// 256(M)x128(N) CTA tile, 256 threads, warp grid 4(m)x2(n), warp tile 64x64.
// EPI=0: fp32 C. EPI=1: split K/V attention layout (N=KVW_).
// EPI=2: split Q_pass attention layout + fp32 rot buffer in C (N=QW_).
#define RSTR    80
#define ATILE   (256 * RSTR)         // 20480 (A: 256 rows)
#define BTILE   (128 * RSTR)         // 10240 (B: 128 rows)
#define STAGE2  (2 * ATILE + 2 * BTILE)  // 61440
#define GSMEM   (2 * STAGE2)         // 122880

template<int EPI>
__global__ __launch_bounds__(256, 1) void gemm_mma_split(
    const __nv_bfloat16* __restrict__ Ah, const __nv_bfloat16* __restrict__ Al,
    const __nv_bfloat16* __restrict__ Bh, const __nv_bfloat16* __restrict__ Bl,
    float* __restrict__ C, int M, int N, int K,
    __nv_bfloat16* __restrict__ Kh, __nv_bfloat16* __restrict__ Kl,
    __nv_bfloat16* __restrict__ Vh, __nv_bfloat16* __restrict__ Vl)
{
    extern __shared__ char smem[];
    const uint32_t sbase = smem_u32(smem);
    const int tid = threadIdx.x;
    const int warp = tid >> 5, lane = tid & 31;
    const int wm = warp >> 1, wn = warp & 1;      // 4 x 2 warp grid
    const int m0 = blockIdx.y * 256, n0 = blockIdx.x * 128;

    const __nv_bfloat16* srcs[4] = {
        Ah + (size_t)m0 * K, Al + (size_t)m0 * K,
        Bh + (size_t)n0 * K, Bl + (size_t)n0 * K };

    float acc[4][8][4];
    #pragma unroll
    for (int i = 0; i < 4; i++)
        #pragma unroll
        for (int j = 0; j < 8; j++)
            #pragma unroll
            for (int k = 0; k < 4; k++) acc[i][j][k] = 0.f;

    const int nch = K / 32;

    // stage: A tiles 1024 chunks each (4/thread), B tiles 512 chunks (2/thread)
    auto load_stage = [&](int ch, int s) {
        const int k0 = ch * 32;
        const uint32_t stg = sbase + (uint32_t)s * STAGE2;
        #pragma unroll
        for (int t = 0; t < 2; t++) {           // Ah, Al
            const uint32_t tb = stg + (uint32_t)t * ATILE;
            #pragma unroll
            for (int it = 0; it < 4; it++) {
                const int i = tid + it * 256;
                const int r = i >> 2, c = i & 3;
                cp16(tb + r * RSTR + c * 16,
                     srcs[t] + (size_t)r * K + k0 + c * 8, true);
            }
        }
        #pragma unroll
        for (int t = 0; t < 2; t++) {           // Bh, Bl
            const uint32_t tb = stg + 2 * ATILE + (uint32_t)t * BTILE;
            #pragma unroll
            for (int it = 0; it < 2; it++) {
                const int i = tid + it * 256;
                const int r = i >> 2, c = i & 3;
                const bool ok = (n0 + r < N);
                const int re = ok ? r : 0;
                cp16(tb + r * RSTR + c * 16,
                     srcs[2 + t] + (size_t)re * K + k0 + c * 8, ok);
            }
        }
    };

    load_stage(0, 0);
    CP_COMMIT();

    const int arow = wm * 64 + (lane & 15);
    const int akof = (lane >> 4) * 8;
    const int brow = wn * 64 + (lane >> 4) * 8 + (lane & 7);
    const int bkof = ((lane >> 3) & 1) * 8;

    for (int ch = 0; ch < nch; ch++) {
        if (ch + 1 < nch) { load_stage(ch + 1, (ch + 1) & 1); CP_COMMIT(); CP_WAIT(1); }
        else             { CP_WAIT(0); }
        __syncthreads();

        const uint32_t sA = sbase + (uint32_t)(ch & 1) * STAGE2;
        #pragma unroll
        for (int kk = 0; kk < 2; kk++) {
            const int ko = kk * 16;
            uint32_t a_h[4][4], a_l[4][4], b_h[8][2], b_l[8][2];
            #pragma unroll
            for (int mt = 0; mt < 4; mt++) {
                const uint32_t ad = sA + (arow + mt * 16) * RSTR + (akof + ko) * 2;
                ldm_x4(a_h[mt], ad);
                ldm_x4(a_l[mt], ad + ATILE);
            }
            #pragma unroll
            for (int p = 0; p < 4; p++) {
                uint32_t r4[4];
                const uint32_t bd = sA + 2 * ATILE +
                                    (brow + p * 16) * RSTR + (bkof + ko) * 2;
                ldm_x4(r4, bd);
                b_h[2*p][0] = r4[0]; b_h[2*p][1] = r4[1];
                b_h[2*p+1][0] = r4[2]; b_h[2*p+1][1] = r4[3];
                ldm_x4(r4, bd + BTILE);
                b_l[2*p][0] = r4[0]; b_l[2*p][1] = r4[1];
                b_l[2*p+1][0] = r4[2]; b_l[2*p+1][1] = r4[3];
            }
            #pragma unroll
            for (int mt = 0; mt < 4; mt++)
                #pragma unroll
                for (int nt = 0; nt < 8; nt++) {
                    mma16816(acc[mt][nt], a_h[mt], b_h[nt]);
                    mma16816(acc[mt][nt], a_h[mt], b_l[nt]);
                    mma16816(acc[mt][nt], a_l[mt], b_h[nt]);
                }
        }
        __syncthreads();
    }

    const int cr = lane >> 2, ccol = (lane & 3) * 2;
    #pragma unroll
    for (int mt = 0; mt < 4; mt++) {
        #pragma unroll
        for (int nt = 0; nt < 8; nt++) {
            const int m = m0 + wm * 64 + mt * 16 + cr;
            const int n = n0 + wn * 64 + nt * 8 + ccol;
            if (EPI == 0) {
                if (n < N) {
                    *reinterpret_cast<float2*>(&C[(size_t)m * N + n]) =
                        make_float2(acc[mt][nt][0], acc[mt][nt][1]);
                    *reinterpret_cast<float2*>(&C[(size_t)(m + 8) * N + n]) =
                        make_float2(acc[mt][nt][2], acc[mt][nt][3]);
                }
            } else if (EPI == 1) {
                // kv layout: n = h*256 + d ; d<128 -> K_pass, d>=128 -> V
                const int hh = n >> 8, d = n & 255;
                #pragma unroll
                for (int rr = 0; rr < 2; rr++) {
                    const int mg = m + rr * 8;
                    const int bb = mg >> 11, tt = mg & 2047;
                    const size_t bht = (size_t)(bb * NH_ + hh) * T_ + tt;
                    const float v0 = acc[mt][nt][rr * 2];
                    const float v1 = acc[mt][nt][rr * 2 + 1];
                    if (d < DN_) {
                        const size_t o = bht * DQK_ + d;
                        *reinterpret_cast<__nv_bfloat162*>(&Kh[o]) = split2_h(v0, v1);
                        *reinterpret_cast<__nv_bfloat162*>(&Kl[o]) = split2_l(v0, v1);
                    } else {
                        const size_t o = bht * DV_ + (d - DN_);
                        *reinterpret_cast<__nv_bfloat162*>(&Vh[o]) = split2_h(v0, v1);
                        *reinterpret_cast<__nv_bfloat162*>(&Vl[o]) = split2_l(v0, v1);
                    }
                }
            } else {
                // q layout: n = h*192 + d ; d<128 -> Q_pass split, d>=128 -> rot fp32
                const int hh = n / DQK_, d = n % DQK_;
                #pragma unroll
                for (int rr = 0; rr < 2; rr++) {
                    const int mg = m + rr * 8;
                    const int bb = mg >> 11, tt = mg & 2047;
                    const size_t bht = (size_t)(bb * NH_ + hh) * T_ + tt;
                    const float v0 = acc[mt][nt][rr * 2];
                    const float v1 = acc[mt][nt][rr * 2 + 1];
                    if (d < DN_) {
                        const size_t o = bht * DQK_ + d;
                        *reinterpret_cast<__nv_bfloat162*>(&Kh[o]) = split2_h(v0, v1);
                        *reinterpret_cast<__nv_bfloat162*>(&Kl[o]) = split2_l(v0, v1);
                    } else {
                        *reinterpret_cast<float2*>(&C[bht * DR_ + (d - DN_)]) =
                            make_float2(v0, v1);
                    }
                }
            }
        }
    }
}

// --------------------------- split / transpose ------------------------------
__global__ __launch_bounds__(256) void split_kernel(
    const float* __restrict__ in, __nv_bfloat16* __restrict__ oh,
    __nv_bfloat16* __restrict__ ol, size_t n)
{
    size_t i = (size_t)blockIdx.x * 256 + threadIdx.x;
    if (i < n) { __nv_bfloat16 h, l; split_bf16(in[i], h, l); oh[i] = h; ol[i] = l; }
}

__global__ __launch_bounds__(256) void tsplit_kernel(
    const float* __restrict__ W, __nv_bfloat16* __restrict__ Th,
    __nv_bfloat16* __restrict__ Tl, int K, int N)
{
    __shared__ float tile[32][33];
    const int kb = blockIdx.y * 32, nb = blockIdx.x * 32;
    const int tx = threadIdx.x & 31, ty = threadIdx.x >> 5;
    #pragma unroll
    for (int j = 0; j < 32; j += 8)
        tile[ty + j][tx] = W[(size_t)(kb + ty + j) * N + nb + tx];
    __syncthreads();
    #pragma unroll
    for (int j = 0; j < 32; j += 8) {
        float v = tile[tx][ty + j];
        __nv_bfloat16 h, l; split_bf16(v, h, l);
        size_t o = (size_t)(nb + ty + j) * K + kb + tx;
        Th[o] = h; Tl[o] = l;
    }
}

// ------------------------------- RMSNorm(+split) ----------------------------
__global__ __launch_bounds__(256) void rmsnorm_split_kernel(
    const float* __restrict__ in, int in_stride,
    const float* __restrict__ scale,
    __nv_bfloat16* __restrict__ oh, __nv_bfloat16* __restrict__ ol, int C)
{
    const int row = blockIdx.x;
    const float* p = in + (size_t)row * in_stride;
    float ss = 0.f;
    for (int c = threadIdx.x; c < C; c += 256) { float v = p[c]; ss = fmaf(v, v, ss); }
    __shared__ float red[8];
    #pragma unroll
    for (int off = 16; off; off >>= 1) ss += __shfl_xor_sync(0xffffffffu, ss, off);
    if ((threadIdx.x & 31) == 0) red[threadIdx.x >> 5] = ss;
    __syncthreads();
    if (threadIdx.x < 8) {
        float v = red[threadIdx.x];
        #pragma unroll
        for (int off = 4; off; off >>= 1) v += __shfl_xor_sync(0xffu, v, off);
        if (threadIdx.x == 0) red[0] = v;
    }
    __syncthreads();
    const float inv = rsqrtf(red[0] / (float)C + 1e-6f);
    for (int c = threadIdx.x; c < C; c += 256) {
        float v = p[c] * inv * scale[c];
        __nv_bfloat16 h, l; split_bf16(v, h, l);
        size_t o = (size_t)row * C + c;
        oh[o] = h; ol[o] = l;
    }
}

// -------------- fused RoPE + per-head split pre-passes ----------------------
__device__ __forceinline__ float rope_elem(const float* base, int e, float pos) {
    const int j = e & 31;
    const float inv_freq = exp2f(-(float)j * (13.287712379549449f / 32.f));
    float s, c;
    sincosf(pos * inv_freq, &s, &c);
    return (e < 32) ? base[e] * c - base[e + 32] * s
                    : base[e] * c + base[e - 32] * s;
}

// Q rot section: reads compact g_qrot [bht][64], writes Q dims 128..191
__global__ __launch_bounds__(256) void qrot_split_kernel(
    const float* __restrict__ qrot, const int* __restrict__ positions,
    __nv_bfloat16* __restrict__ Qh, __nv_bfloat16* __restrict__ Ql)
{
    const size_t total = (size_t)B_ * NH_ * T_ * (DR_ / 2);
    size_t idx = (size_t)blockIdx.x * 256 + threadIdx.x;
    if (idx >= total) return;
    const int dp = idx % (DR_ / 2);
    const size_t bht = idx / (DR_ / 2);
    const int t = bht % T_;
    const int b = (bht / T_) >> 4;
    const float* rot = qrot + bht * DR_;
    const float pos = (float)positions[b * T_ + t];
    const int e0 = 2 * dp;
    const float v0 = rope_elem(rot, e0, pos);
    const float v1 = rope_elem(rot, e0 + 1, pos);
    const size_t o = bht * DQK_ + DN_ + e0;
    *reinterpret_cast<__nv_bfloat162*>(&Qh[o]) = split2_h(v0, v1);
    *reinterpret_cast<__nv_bfloat162*>(&Ql[o]) = split2_l(v0, v1);
}

// K rot section: dims 128..191, roped ckv columns (shared across heads)
__global__ __launch_bounds__(256) void krot_split_kernel(
    const float* __restrict__ qa2, const int* __restrict__ positions,
    __nv_bfloat16* __restrict__ Kh, __nv_bfloat16* __restrict__ Kl)
{
    const size_t total = (size_t)B_ * NH_ * T_ * (DR_ / 2);
    size_t idx = (size_t)blockIdx.x * 256 + threadIdx.x;
    if (idx >= total) return;
    const int dp = idx % (DR_ / 2);
    const size_t bht = idx / (DR_ / 2);
    const int t = bht % T_;
    const int b = (bht / T_) >> 4;
    const float* rot = qa2 + ((size_t)(b * T_ + t)) * QAW_ + QLR_ + KVLR_;
    const float pos = (float)positions[b * T_ + t];
    const int e0 = 2 * dp;
    const float v0 = rope_elem(rot, e0, pos);
    const float v1 = rope_elem(rot, e0 + 1, pos);
    const size_t o = bht * DQK_ + DN_ + e0;
    *reinterpret_cast<__nv_bfloat162*>(&Kh[o]) = split2_h(v0, v1);
    *reinterpret_cast<__nv_bfloat162*>(&Kl[o]) = split2_l(v0, v1);
}

// ------------------- tensor-core flash attention (split bf16) ---------------
#define QSTR 400
#define VSTR 272
#define SQH  0
#define SSTG (128 * QSTR)
#define STG_KL 25600
#define STG_VH 51200
#define STG_VL 68608
#define STG_SZ 86016
#define ASMEM (SSTG + 2 * STG_SZ)   // 223232

__global__ __launch_bounds__(256) void attn_mma_kernel(
    const __nv_bfloat16* __restrict__ Qh, const __nv_bfloat16* __restrict__ Ql,
    const __nv_bfloat16* __restrict__ Kh, const __nv_bfloat16* __restrict__ Kl,
    const __nv_bfloat16* __restrict__ Vh, const __nv_bfloat16* __restrict__ Vl,
    __nv_bfloat16* __restrict__ oh, __nv_bfloat16* __restrict__ ol)
{
    extern __shared__ char smem[];
    const uint32_t sbase = smem_u32(smem);
    const int tid = threadIdx.x, warp = tid >> 5, lane = tid & 31;
    const int qblk = gridDim.x - 1 - blockIdx.x;
    const int h = blockIdx.y, b = blockIdx.z;
    const int q0 = qblk * 128;
    const int bh = b * NH_ + h;

    const int arow = warp * 16 + (lane & 15);
    const int akof = (lane >> 4) * 8;
    const int brow = (lane >> 4) * 8 + (lane & 7);
    const int bkof = ((lane >> 3) & 1) * 8;
    const int vkof = ((lane >> 3) & 1) * 8 + (lane & 7);
    const int vnof = (lane >> 4) * 8;

    const size_t qoff = ((size_t)bh * T_ + q0) * DQK_;
    for (int i = tid; i < 128 * 24; i += 256) {
        const int r = i / 24, c = i % 24;
        cp16(sbase + SSTG + r * QSTR + c * 16, Ql + qoff + (size_t)r * DQK_ + c * 8, true);
    }
    CP_COMMIT(); CP_WAIT(0);
    __syncthreads();
    uint32_t ql[12][4];
    #pragma unroll
    for (int ks = 0; ks < 12; ks++)
        ldm_x4(ql[ks], sbase + SSTG + arow * QSTR + (ks * 16 + akof) * 2);
    __syncthreads();

    auto load_kv = [&](int ch, int s) {
        const int kk0 = ch * 64;
        const size_t koff = ((size_t)bh * T_ + kk0) * DQK_;
        const size_t voff = ((size_t)bh * T_ + kk0) * DV_;
        const uint32_t stg = sbase + SSTG + (uint32_t)s * STG_SZ;
        for (int i = tid; i < 64 * 24; i += 256) {
            const int r = i / 24, c = i % 24;
            cp16(stg + r * QSTR + c * 16, Kh + koff + (size_t)r * DQK_ + c * 8, true);
            cp16(stg + STG_KL + r * QSTR + c * 16, Kl + koff + (size_t)r * DQK_ + c * 8, true);
        }
        for (int i = tid; i < 64 * 16; i += 256) {
            const int r = i >> 4, c = i & 15;
            cp16(stg + STG_VH + r * VSTR + c * 16, Vh + voff + (size_t)r * DV_ + c * 8, true);
            cp16(stg + STG_VL + r * VSTR + c * 16, Vl + voff + (size_t)r * DV_ + c * 8, true);
        }
    };

    for (int i = tid; i < 128 * 24; i += 256) {
        const int r = i / 24, c = i % 24;
        cp16(sbase + SQH + r * QSTR + c * 16, Qh + qoff + (size_t)r * DQK_ + c * 8, true);
    }
    load_kv(0, 0);
    CP_COMMIT();

    float S[8][4], O[16][4];
    #pragma unroll
    for (int t = 0; t < 16; t++)
        #pragma unroll
        for (int e = 0; e < 4; e++) O[t][e] = 0.f;
    float m0 = -1e30f, m1 = -1e30f, l0 = 0.f, l1 = 0.f;
    const float scale = 0.07216878364870323f;  // 192^-0.5

    const int r0g = q0 + warp * 16 + (lane >> 2);
    const int r1g = r0g + 8;
    const int wrow_max = q0 + warp * 16 + 15;

    const int nch = 2 * qblk + 2;
    for (int ch = 0; ch < nch; ch++) {
        const int k0 = ch * 64;
        if (ch + 1 < nch) { load_kv(ch + 1, (ch + 1) & 1); CP_COMMIT(); CP_WAIT(1); }
        else              { CP_WAIT(0); }
        __syncthreads();

        const bool active = (k0 <= wrow_max);
        if (active) {
            const uint32_t stg = sbase + SSTG + (uint32_t)(ch & 1) * STG_SZ;

            #pragma unroll
            for (int t = 0; t < 8; t++)
                #pragma unroll
                for (int e = 0; e < 4; e++) S[t][e] = 0.f;
            #pragma unroll
            for (int ks = 0; ks < 12; ks++) {
                uint32_t ah4[4];
                ldm_x4(ah4, sbase + SQH + arow * QSTR + (ks * 16 + akof) * 2);
                #pragma unroll
                for (int p = 0; p < 4; p++) {
                    uint32_t rh[4], rl[4];
                    const uint32_t bd = stg + (p * 16 + brow) * QSTR
                                        + (ks * 16 + bkof) * 2;
                    ldm_x4(rh, bd);
                    ldm_x4(rl, bd + STG_KL);
                    mma16816(S[2*p],   ah4, rh);
                    mma16816(S[2*p],   ah4, rl);
                    mma16816(S[2*p],   ql[ks], rh);
                    mma16816(S[2*p+1], ah4, rh + 2);
                    mma16816(S[2*p+1], ah4, rl + 2);
                    mma16816(S[2*p+1], ql[ks], rh + 2);
                }
            }

            const bool dm = (k0 + 63 > q0);
            #pragma unroll
            for (int t = 0; t < 8; t++) {
                #pragma unroll
                for (int e = 0; e < 4; e++) {
                    float v = S[t][e] * scale;
                    if (dm) {
                        const int kg = k0 + t * 8 + (lane & 3) * 2 + (e & 1);
                        const int rg = (e < 2) ? r0g : r1g;
                        if (kg > rg) v = -1e30f;
                    }
                    S[t][e] = v;
                }
            }

            float mx0 = -1e30f, mx1 = -1e30f;
            #pragma unroll
            for (int t = 0; t < 8; t++) {
                mx0 = fmaxf(mx0, fmaxf(S[t][0], S[t][1]));
                mx1 = fmaxf(mx1, fmaxf(S[t][2], S[t][3]));
            }
            mx0 = fmaxf(mx0, __shfl_xor_sync(0xffffffffu, mx0, 1));
            mx0 = fmaxf(mx0, __shfl_xor_sync(0xffffffffu, mx0, 2));
            mx1 = fmaxf(mx1, __shfl_xor_sync(0xffffffffu, mx1, 1));
            mx1 = fmaxf(mx1, __shfl_xor_sync(0xffffffffu, mx1, 2));
            const float mn0 = fmaxf(m0, mx0), mn1 = fmaxf(m1, mx1);
            const float a0 = __expf(m0 - mn0), a1 = __expf(m1 - mn1);
            float s0 = 0.f, s1 = 0.f;
            #pragma unroll
            for (int t = 0; t < 8; t++) {
                S[t][0] = __expf(S[t][0] - mn0); s0 += S[t][0];
                S[t][1] = __expf(S[t][1] - mn0); s0 += S[t][1];
                S[t][2] = __expf(S[t][2] - mn1); s1 += S[t][2];
                S[t][3] = __expf(S[t][3] - mn1); s1 += S[t][3];
            }
            s0 += __shfl_xor_sync(0xffffffffu, s0, 1);
            s0 += __shfl_xor_sync(0xffffffffu, s0, 2);
            s1 += __shfl_xor_sync(0xffffffffu, s1, 1);
            s1 += __shfl_xor_sync(0xffffffffu, s1, 2);
            l0 = l0 * a0 + s0;  l1 = l1 * a1 + s1;
            m0 = mn0;  m1 = mn1;
            #pragma unroll
            for (int t = 0; t < 16; t++) {
                O[t][0] *= a0; O[t][1] *= a0; O[t][2] *= a1; O[t][3] *= a1;
            }

            #pragma unroll
            for (int kt = 0; kt < 4; kt++) {
                uint32_t pah[4], pal[4];
                #pragma unroll
                for (int i = 0; i < 4; i++) {
                    const float p0 = S[2*kt + (i >> 1)][(i & 1) * 2];
                    const float p1 = S[2*kt + (i >> 1)][(i & 1) * 2 + 1];
                    __nv_bfloat162 hh = split2_h(p0, p1);
                    __nv_bfloat162 ll = split2_l(p0, p1);
                    pah[i] = *reinterpret_cast<uint32_t*>(&hh);
                    pal[i] = *reinterpret_cast<uint32_t*>(&ll);
                }
                #pragma unroll
                for (int vt = 0; vt < 8; vt++) {
                    uint32_t rh[4], rl[4];
                    const uint32_t vd = stg + STG_VH + (kt * 16 + vkof) * VSTR
                                        + (vt * 16 + vnof) * 2;
                    ldm_x4_t(rh, vd);
                    ldm_x4_t(rl, vd + (STG_VL - STG_VH));
                    mma16816(O[2*vt],   pah, rh);
                    mma16816(O[2*vt],   pah, rl);
                    mma16816(O[2*vt],   pal, rh);
                    mma16816(O[2*vt+1], pah, rh + 2);
                    mma16816(O[2*vt+1], pah, rl + 2);
                    mma16816(O[2*vt+1], pal, rh + 2);
                }
            }
        }
        __syncthreads();
    }

    const float i0 = 1.f / l0, i1 = 1.f / l1;
    const size_t obase0 = ((size_t)(b * T_ + r0g)) * (NH_ * DV_) + h * DV_;
    const size_t obase1 = ((size_t)(b * T_ + r1g)) * (NH_ * DV_) + h * DV_;
    #pragma unroll
    for (int t = 0; t < 16; t++) {
        const int d = t * 8 + (lane & 3) * 2;
        *reinterpret_cast<__nv_bfloat162*>(&oh[obase0 + d]) =
            split2_h(O[t][0] * i0, O[t][1] * i0);
        *reinterpret_cast<__nv_bfloat162*>(&ol[obase0 + d]) =
            split2_l(O[t][0] * i0, O[t][1] * i0);
        *reinterpret_cast<__nv_bfloat162*>(&oh[obase1 + d]) =
            split2_h(O[t][2] * i1, O[t][3] * i1);
        *reinterpret_cast<__nv_bfloat162*>(&ol[obase1 + d]) =
            split2_l(O[t][2] * i1, O[t][3] * i1);
    }
}

// ------------------------------- launcher -----------------------------------
static inline void run_gemm(const __nv_bfloat16* Ah, const __nv_bfloat16* Al,
                            const __nv_bfloat16* Bh, const __nv_bfloat16* Bl,
                            float* C, int M, int N, int K)
{
    dim3 grid((N + 127) / 128, M / 256);
    gemm_mma_split<0><<<grid, 256, GSMEM>>>(Ah, Al, Bh, Bl, C, M, N, K,
                                            nullptr, nullptr, nullptr, nullptr);
}

extern "C" void kernel_launch(void* const* d_in, const int* in_sizes, int n_in,
                              void* d_out, int out_size)
{
    const float* x         = (const float*)d_in[0];
    const int*   positions = (const int*)  d_in[2];
    const float* wqa       = (const float*)d_in[3];
    const float* qa_scale  = (const float*)d_in[4];
    const float* wqb       = (const float*)d_in[5];
    const float* wkva      = (const float*)d_in[6];
    const float* kva_scale = (const float*)d_in[7];
    const float* wkvb      = (const float*)d_in[8];
    const float* wo        = (const float*)d_in[9];
    float* out = (float*)d_out;

    cudaFuncSetAttribute(gemm_mma_split<0>,
                         cudaFuncAttributeMaxDynamicSharedMemorySize, GSMEM);
    cudaFuncSetAttribute(gemm_mma_split<1>,
                         cudaFuncAttributeMaxDynamicSharedMemorySize, GSMEM);
    cudaFuncSetAttribute(gemm_mma_split<2>,
                         cudaFuncAttributeMaxDynamicSharedMemorySize, GSMEM);
    cudaFuncSetAttribute(attn_mma_kernel,
                         cudaFuncAttributeMaxDynamicSharedMemorySize, ASMEM);

    float *qa2, *qrot;
    cudaGetSymbolAddress((void**)&qa2,  g_qa2);
    cudaGetSymbolAddress((void**)&qrot, g_qrot);
    __nv_bfloat16 *xh, *xl, *qanh, *qanl, *kvnh, *kvnl, *ath, *atl;
    __nv_bfloat16 *wqkvah, *wqkval, *wqbh, *wqbl, *wkvbh, *wkvbl, *woh, *wol;
    __nv_bfloat16 *Qh, *Ql, *Kh, *Kl, *Vh, *Vl;
    cudaGetSymbolAddress((void**)&xh,   g_x_h);   cudaGetSymbolAddress((void**)&xl,   g_x_l);
    cudaGetSymbolAddress((void**)&qanh, g_qan_h); cudaGetSymbolAddress((void**)&qanl, g_qan_l);
    cudaGetSymbolAddress((void**)&kvnh, g_kvn_h); cudaGetSymbolAddress((void**)&kvnl, g_kvn_l);
    cudaGetSymbolAddress((void**)&ath,  g_att_h); cudaGetSymbolAddress((void**)&atl,  g_att_l);
    cudaGetSymbolAddress((void**)&wqkvah, g_wqkva_h);
    cudaGetSymbolAddress((void**)&wqkval, g_wqkva_l);
    cudaGetSymbolAddress((void**)&wqbh, g_wqb_h); cudaGetSymbolAddress((void**)&wqbl, g_wqb_l);
    cudaGetSymbolAddress((void**)&wkvbh, g_wkvb_h); cudaGetSymbolAddress((void**)&wkvbl, g_wkvb_l);
    cudaGetSymbolAddress((void**)&woh,  g_wo_h);  cudaGetSymbolAddress((void**)&wol,  g_wo_l);
    cudaGetSymbolAddress((void**)&Qh, g_Qh); cudaGetSymbolAddress((void**)&Ql, g_Ql);
    cudaGetSymbolAddress((void**)&Kh, g_Kh); cudaGetSymbolAddress((void**)&Kl, g_Kl);
    cudaGetSymbolAddress((void**)&Vh, g_Vh); cudaGetSymbolAddress((void**)&Vl, g_Vl);

    // 0. split x; transpose+split weights
    {
        size_t n = (size_t)ROWS_ * HID_;
        split_kernel<<<(unsigned)((n + 255) / 256), 256>>>(x, xh, xl, n);
        tsplit_kernel<<<dim3(QLR_/32, HID_/32), 256>>>(wqa, wqkvah, wqkval, HID_, QLR_);
        tsplit_kernel<<<dim3(CKVW_/32, HID_/32), 256>>>(
            wkva, wqkvah + (size_t)QLR_ * HID_, wqkval + (size_t)QLR_ * HID_, HID_, CKVW_);
        tsplit_kernel<<<dim3(QW_/32, QLR_/32), 256>>>(wqb, wqbh, wqbl, QLR_, QW_);
        tsplit_kernel<<<dim3(KVW_/32, KVLR_/32), 256>>>(wkvb, wkvbh, wkvbl, KVLR_, KVW_);
        tsplit_kernel<<<dim3(HID_/32, (NH_*DV_)/32), 256>>>(wo, woh, wol, NH_*DV_, HID_);
    }
    // 1. merged [qa | ckv] = x @ [wqa | wkva]
    run_gemm(xh, xl, wqkvah, wqkval, qa2, ROWS_, QAW_, HID_);
    // 2. qan = rmsnorm(qa2[:, :1536])
    rmsnorm_split_kernel<<<ROWS_, 256>>>(qa2, QAW_, qa_scale, qanh, qanl, QLR_);
    // 3. q GEMM: epilogue writes split Q_pass + fp32 rot buffer
    {
        dim3 grid(QW_ / 128, ROWS_ / 256);
        gemm_mma_split<2><<<grid, 256, GSMEM>>>(
            qanh, qanl, wqbh, wqbl, qrot, ROWS_, QW_, QLR_, Qh, Ql, nullptr, nullptr);
    }
    // 4. kvn = rmsnorm(qa2[:, 1536:2048])
    rmsnorm_split_kernel<<<ROWS_, 256>>>(qa2 + QLR_, QAW_, kva_scale, kvnh, kvnl, KVLR_);
    // 5. kv GEMM: epilogue writes split K_pass/V directly
    {
        dim3 grid(KVW_ / 128, ROWS_ / 256);
        gemm_mma_split<1><<<grid, 256, GSMEM>>>(
            kvnh, kvnl, wkvbh, wkvbl, nullptr, ROWS_, KVW_, KVLR_, Kh, Kl, Vh, Vl);
    }
    // 6. rot-only rope + split for Q and K
    {
        size_t nr = (size_t)B_ * NH_ * T_ * (DR_ / 2);
        qrot_split_kernel<<<(unsigned)((nr + 255) / 256), 256>>>(qrot, positions, Qh, Ql);
        krot_split_kernel<<<(unsigned)((nr + 255) / 256), 256>>>(qa2, positions, Kh, Kl);
    }
    // 7. tensor-core flash attention
    {
        dim3 grid(T_ / 128, NH_, B_);
        attn_mma_kernel<<<grid, 256, ASMEM>>>(Qh, Ql, Kh, Kl, Vh, Vl, ath, atl);
    }
    // 8. out = attn @ wo
    run_gemm(ath, atl, woh, wol, out, ROWS_, HID_, NH_ * DV_);
}

// round 16
// speedup vs baseline: 1.0687x; 1.0687x over previous
#include <cuda_runtime.h>
#include <cuda_bf16.h>
#include <math.h>
#include <cstdint>

// DeepseekV3 MLA attention forward.
// GEMMs + flash attention on mma.sync bf16 with hi+lo split precision.
// R15: R12 GEMM geometry (128x128, occ 2) restored; q+kv projections merged
// into one launch (blockIdx.z) to pack wave tails.

#define B_   2
#define T_   2048
#define HID_ 2048
#define NH_  16
#define QLR_ 1536
#define KVLR_ 512
#define DN_  128
#define DR_  64
#define DQK_ 192
#define DV_  128
#define ROWS_ (B_*T_)           // 4096
#define QW_  (NH_*DQK_)         // 3072
#define KVW_ (NH_*(DN_+DV_))    // 4096
#define CKVW_ (KVLR_+DR_)       // 576
#define QAW_ (QLR_+CKVW_)       // 2112

// ------------------------- scratch (device globals) -------------------------
__device__ float g_qa2 [(size_t)ROWS_*QAW_];   // [qa(1536) | ckv(576)]
__device__ float g_qrot[(size_t)B_*NH_*T_*DR_]; // un-roped q rot dims

// bf16 split activations
__device__ __nv_bfloat16 g_x_h  [(size_t)ROWS_*HID_];
__device__ __nv_bfloat16 g_x_l  [(size_t)ROWS_*HID_];
__device__ __nv_bfloat16 g_qan_h[(size_t)ROWS_*QLR_];
__device__ __nv_bfloat16 g_qan_l[(size_t)ROWS_*QLR_];
__device__ __nv_bfloat16 g_kvn_h[(size_t)ROWS_*KVLR_];
__device__ __nv_bfloat16 g_kvn_l[(size_t)ROWS_*KVLR_];
__device__ __nv_bfloat16 g_att_h[(size_t)ROWS_*(NH_*DV_)];
__device__ __nv_bfloat16 g_att_l[(size_t)ROWS_*(NH_*DV_)];

// per-head split Q/K/V for attention ([bh][t][d])
__device__ __nv_bfloat16 g_Qh[(size_t)B_*NH_*T_*DQK_];
__device__ __nv_bfloat16 g_Ql[(size_t)B_*NH_*T_*DQK_];
__device__ __nv_bfloat16 g_Kh[(size_t)B_*NH_*T_*DQK_];
__device__ __nv_bfloat16 g_Kl[(size_t)B_*NH_*T_*DQK_];
__device__ __nv_bfloat16 g_Vh[(size_t)B_*NH_*T_*DV_];
__device__ __nv_bfloat16 g_Vl[(size_t)B_*NH_*T_*DV_];

// bf16 split transposed weights [N,K]
__device__ __nv_bfloat16 g_wqkva_h[(size_t)QAW_*HID_];
__device__ __nv_bfloat16 g_wqkva_l[(size_t)QAW_*HID_];
__device__ __nv_bfloat16 g_wqb_h [(size_t)QW_*QLR_];
__device__ __nv_bfloat16 g_wqb_l [(size_t)QW_*QLR_];
__device__ __nv_bfloat16 g_wkvb_h[(size_t)KVW_*KVLR_];
__device__ __nv_bfloat16 g_wkvb_l[(size_t)KVW_*KVLR_];
__device__ __nv_bfloat16 g_wo_h  [(size_t)HID_*(NH_*DV_)];
__device__ __nv_bfloat16 g_wo_l  [(size_t)HID_*(NH_*DV_)];

// ------------------------------ PTX helpers ---------------------------------
__device__ __forceinline__ uint32_t smem_u32(const void* p) {
    uint32_t a;
    asm("{ .reg .u64 t; cvta.to.shared.u64 t, %1; cvt.u32.u64 %0, t; }"
        : "=r"(a) : "l"(p));
    return a;
}
__device__ __forceinline__ void cp16(uint32_t s, const void* g, bool ok) {
    asm volatile("cp.async.cg.shared.global [%0], [%1], 16, %2;"
        :: "r"(s), "l"(g), "r"(ok ? 16 : 0));
}
#define CP_COMMIT() asm volatile("cp.async.commit_group;" ::: "memory")
#define CP_WAIT(n)  asm volatile("cp.async.wait_group %0;" :: "n"(n) : "memory")

__device__ __forceinline__ void ldm_x4(uint32_t* r, uint32_t addr) {
    asm volatile("ldmatrix.sync.aligned.m8n8.x4.shared.b16 {%0,%1,%2,%3}, [%4];"
        : "=r"(r[0]), "=r"(r[1]), "=r"(r[2]), "=r"(r[3]) : "r"(addr));
}
__device__ __forceinline__ void ldm_x4_t(uint32_t* r, uint32_t addr) {
    asm volatile("ldmatrix.sync.aligned.m8n8.x4.trans.shared.b16 {%0,%1,%2,%3}, [%4];"
        : "=r"(r[0]), "=r"(r[1]), "=r"(r[2]), "=r"(r[3]) : "r"(addr));
}
__device__ __forceinline__ void mma16816(float* d, const uint32_t* a, const uint32_t* b) {
    asm volatile(
        "mma.sync.aligned.m16n8k16.row.col.f32.bf16.bf16.f32 "
        "{%0,%1,%2,%3}, {%4,%5,%6,%7}, {%8,%9}, {%0,%1,%2,%3};"
        : "+f"(d[0]), "+f"(d[1]), "+f"(d[2]), "+f"(d[3])
        : "r"(a[0]), "r"(a[1]), "r"(a[2]), "r"(a[3]), "r"(b[0]), "r"(b[1]));
}
__device__ __forceinline__ void split_bf16(float v, __nv_bfloat16& h, __nv_bfloat16& l) {
    h = __float2bfloat16_rn(v);
    l = __float2bfloat16_rn(v - __bfloat162float(h));
}
__device__ __forceinline__ __nv_bfloat162 split2_h(float a, float b) {
    return __nv_bfloat162(__float2bfloat16_rn(a), __float2bfloat16_rn(b));
}
__device__ __forceinline__ __nv_bfloat162 split2_l(float a, float b) {
    __nv_bfloat16 ha = __float2bfloat16_rn(a), hb = __float2bfloat16_rn(b);
    return __nv_bfloat162(__float2bfloat16_rn(a - __bfloat162float(ha)),
                          __float2bfloat16_rn(b - __bfloat162float(hb)));
}

// ---------------- split-bf16 GEMM core (128x128 tile, Kc=32, occ 2) ----------
#define RSTR    80
#define TILE_B  (128 * RSTR)         // 10240
#define STAGE_B (4 * TILE_B)         // 40960
#define GSMEM   (2 * STAGE_B)        // 81920

// Shared mainloop: computes 128x128 tile accumulators.
struct GemmCore {
    float acc[4][4][4];
    int cr, ccol, wm, wn;

    __device__ __forceinline__ void run(
        uint32_t sbase, int tid,
        const __nv_bfloat16* Ah, const __nv_bfloat16* Al,
        const __nv_bfloat16* Bh, const __nv_bfloat16* Bl,
        int m0, int n0, int N, int K)
    {
        const int warp = tid >> 5, lane = tid & 31;
        wm = warp >> 2; wn = warp & 3;
        cr = lane >> 2; ccol = (lane & 3) * 2;

        const __nv_bfloat16* srcs[4] = {
            Ah + (size_t)m0 * K, Al + (size_t)m0 * K,
            Bh + (size_t)n0 * K, Bl + (size_t)n0 * K };

        #pragma unroll
        for (int i = 0; i < 4; i++)
            #pragma unroll
            for (int j = 0; j < 4; j++)
                #pragma unroll
                for (int k = 0; k < 4; k++) acc[i][j][k] = 0.f;

        const int nch = K / 32;

        auto load_stage = [&](int ch, int s) {
            const int k0 = ch * 32;
            #pragma unroll
            for (int t = 0; t < 4; t++) {
                const uint32_t tb = sbase + (uint32_t)s * STAGE_B + (uint32_t)t * TILE_B;
                #pragma unroll
                for (int it = 0; it < 2; it++) {
                    const int i = tid + it * 256;
                    const int r = i >> 2, c = i & 3;
                    const bool ok = (t < 2) || (n0 + r < N);
                    const int re = ok ? r : 0;
                    cp16(tb + r * RSTR + c * 16,
                         srcs[t] + (size_t)re * K + k0 + c * 8, ok);
                }
            }
        };

        load_stage(0, 0);
        CP_COMMIT();

        const int arow = wm * 64 + (lane & 15);
        const int akof = (lane >> 4) * 8;
        const int brow = wn * 32 + (lane >> 4) * 8 + (lane & 7);
        const int bkof = ((lane >> 3) & 1) * 8;

        for (int ch = 0; ch < nch; ch++) {
            if (ch + 1 < nch) { load_stage(ch + 1, (ch + 1) & 1); CP_COMMIT(); CP_WAIT(1); }
            else             { CP_WAIT(0); }
            __syncthreads();

            const uint32_t sA = sbase + (uint32_t)(ch & 1) * STAGE_B;
            #pragma unroll
            for (int kk = 0; kk < 2; kk++) {
                const int ko = kk * 16;
                uint32_t a_h[4][4], a_l[4][4], b_h[4][2], b_l[4][2];
                #pragma unroll
                for (int mt = 0; mt < 4; mt++) {
                    const uint32_t ad = sA + (arow + mt * 16) * RSTR + (akof + ko) * 2;
                    ldm_x4(a_h[mt], ad);
                    ldm_x4(a_l[mt], ad + TILE_B);
                }
                #pragma unroll
                for (int p = 0; p < 2; p++) {
                    uint32_t r4[4];
                    const uint32_t bd = sA + 2 * TILE_B +
                                        (brow + p * 16) * RSTR + (bkof + ko) * 2;
                    ldm_x4(r4, bd);
                    b_h[2*p][0] = r4[0]; b_h[2*p][1] = r4[1];
                    b_h[2*p+1][0] = r4[2]; b_h[2*p+1][1] = r4[3];
                    ldm_x4(r4, bd + TILE_B);
                    b_l[2*p][0] = r4[0]; b_l[2*p][1] = r4[1];
                    b_l[2*p+1][0] = r4[2]; b_l[2*p+1][1] = r4[3];
                }
                #pragma unroll
                for (int mt = 0; mt < 4; mt++)
                    #pragma unroll
                    for (int nt = 0; nt < 4; nt++) {
                        mma16816(acc[mt][nt], a_h[mt], b_h[nt]);
                        mma16816(acc[mt][nt], a_h[mt], b_l[nt]);
                        mma16816(acc[mt][nt], a_l[mt], b_h[nt]);
                    }
            }
            __syncthreads();
        }
    }
};

// EPI=0 GEMM (fp32 C) for GEMM1 and wo
__global__ __launch_bounds__(256, 2) void gemm_mma_f32(
    const __nv_bfloat16* __restrict__ Ah, const __nv_bfloat16* __restrict__ Al,
    const __nv_bfloat16* __restrict__ Bh, const __nv_bfloat16* __restrict__ Bl,
    float* __restrict__ C, int M, int N, int K)
{
    extern __shared__ char smem[];
    const uint32_t sbase = smem_u32(smem);
    const int tid = threadIdx.x;
    const int m0 = blockIdx.y * 128, n0 = blockIdx.x * 128;

    GemmCore g;
    g.run(sbase, tid, Ah, Al, Bh, Bl, m0, n0, N, K);

    #pragma unroll
    for (int mt = 0; mt < 4; mt++) {
        #pragma unroll
        for (int nt = 0; nt < 4; nt++) {
            const int m = m0 + g.wm * 64 + mt * 16 + g.cr;
            const int n = n0 + g.wn * 32 + nt * 8 + g.ccol;
            if (n < N) {
                *reinterpret_cast<float2*>(&C[(size_t)m * N + n]) =
                    make_float2(g.acc[mt][nt][0], g.acc[mt][nt][1]);
                *reinterpret_cast<float2*>(&C[(size_t)(m + 8) * N + n]) =
                    make_float2(g.acc[mt][nt][2], g.acc[mt][nt][3]);
            }
        }
    }
}

// Merged q+kv projection GEMM. blockIdx.z = 0: q (N=3072, K=1536, EPI2 layout);
// blockIdx.z = 1: kv (N=4096, K=512, EPI1 layout).
__global__ __launch_bounds__(256, 2) void gemm_mma_qkv(
    const __nv_bfloat16* __restrict__ QAh, const __nv_bfloat16* __restrict__ QAl,
    const __nv_bfloat16* __restrict__ QBh, const __nv_bfloat16* __restrict__ QBl,
    const __nv_bfloat16* __restrict__ KAh, const __nv_bfloat16* __restrict__ KAl,
    const __nv_bfloat16* __restrict__ KBh, const __nv_bfloat16* __restrict__ KBl,
    float* __restrict__ qrot,
    __nv_bfloat16* __restrict__ Qh, __nv_bfloat16* __restrict__ Ql,
    __nv_bfloat16* __restrict__ Kh, __nv_bfloat16* __restrict__ Kl,
    __nv_bfloat16* __restrict__ Vh, __nv_bfloat16* __restrict__ Vl)
{
    extern __shared__ char smem[];
    const uint32_t sbase = smem_u32(smem);
    const int tid = threadIdx.x;
    const int z = blockIdx.z;
    if (z == 0 && blockIdx.x >= QW_ / 128) return;

    const int m0 = blockIdx.y * 128, n0 = blockIdx.x * 128;

    GemmCore g;
    if (z == 0) g.run(sbase, tid, QAh, QAl, QBh, QBl, m0, n0, QW_, QLR_);
    else        g.run(sbase, tid, KAh, KAl, KBh, KBl, m0, n0, KVW_, KVLR_);

    #pragma unroll
    for (int mt = 0; mt < 4; mt++) {
        #pragma unroll
        for (int nt = 0; nt < 4; nt++) {
            const int m = m0 + g.wm * 64 + mt * 16 + g.cr;
            const int n = n0 + g.wn * 32 + nt * 8 + g.ccol;
            if (z == 1) {
                // kv layout: n = h*256 + d ; d<128 -> K_pass, d>=128 -> V
                const int hh = n >> 8, d = n & 255;
                #pragma unroll
                for (int rr = 0; rr < 2; rr++) {
                    const int mg = m + rr * 8;
                    const int bb = mg >> 11, tt = mg & 2047;
                    const size_t bht = (size_t)(bb * NH_ + hh) * T_ + tt;
                    const float v0 = g.acc[mt][nt][rr * 2];
                    const float v1 = g.acc[mt][nt][rr * 2 + 1];
                    if (d < DN_) {
                        const size_t o = bht * DQK_ + d;
                        *reinterpret_cast<__nv_bfloat162*>(&Kh[o]) = split2_h(v0, v1);
                        *reinterpret_cast<__nv_bfloat162*>(&Kl[o]) = split2_l(v0, v1);
                    } else {
                        const size_t o = bht * DV_ + (d - DN_);
                        *reinterpret_cast<__nv_bfloat162*>(&Vh[o]) = split2_h(v0, v1);
                        *reinterpret_cast<__nv_bfloat162*>(&Vl[o]) = split2_l(v0, v1);
                    }
                }
            } else {
                // q layout: n = h*192 + d ; d<128 -> Q_pass split, d>=128 -> rot fp32
                const int hh = n / DQK_, d = n % DQK_;
                #pragma unroll
                for (int rr = 0; rr < 2; rr++) {
                    const int mg = m + rr * 8;
                    const int bb = mg >> 11, tt = mg & 2047;
                    const size_t bht = (size_t)(bb * NH_ + hh) * T_ + tt;
                    const float v0 = g.acc[mt][nt][rr * 2];
                    const float v1 = g.acc[mt][nt][rr * 2 + 1];
                    if (d < DN_) {
                        const size_t o = bht * DQK_ + d;
                        *reinterpret_cast<__nv_bfloat162*>(&Qh[o]) = split2_h(v0, v1);
                        *reinterpret_cast<__nv_bfloat162*>(&Ql[o]) = split2_l(v0, v1);
                    } else {
                        *reinterpret_cast<float2*>(&qrot[bht * DR_ + (d - DN_)]) =
                            make_float2(v0, v1);
                    }
                }
            }
        }
    }
}

// --------------------------- split / transpose ------------------------------
__global__ __launch_bounds__(256) void split_kernel(
    const float* __restrict__ in, __nv_bfloat16* __restrict__ oh,
    __nv_bfloat16* __restrict__ ol, size_t n)
{
    size_t i = (size_t)blockIdx.x * 256 + threadIdx.x;
    if (i < n) { __nv_bfloat16 h, l; split_bf16(in[i], h, l); oh[i] = h; ol[i] = l; }
}

__global__ __launch_bounds__(256) void tsplit_kernel(
    const float* __restrict__ W, __nv_bfloat16* __restrict__ Th,
    __nv_bfloat16* __restrict__ Tl, int K, int N)
{
    __shared__ float tile[32][33];
    const int kb = blockIdx.y * 32, nb = blockIdx.x * 32;
    const int tx = threadIdx.x & 31, ty = threadIdx.x >> 5;
    #pragma unroll
    for (int j = 0; j < 32; j += 8)
        tile[ty + j][tx] = W[(size_t)(kb + ty + j) * N + nb + tx];
    __syncthreads();
    #pragma unroll
    for (int j = 0; j < 32; j += 8) {
        float v = tile[tx][ty + j];
        __nv_bfloat16 h, l; split_bf16(v, h, l);
        size_t o = (size_t)(nb + ty + j) * K + kb + tx;
        Th[o] = h; Tl[o] = l;
    }
}

// ------------------------------- RMSNorm(+split) ----------------------------
__global__ __launch_bounds__(256) void rmsnorm_split_kernel(
    const float* __restrict__ in, int in_stride,
    const float* __restrict__ scale,
    __nv_bfloat16* __restrict__ oh, __nv_bfloat16* __restrict__ ol, int C)
{
    const int row = blockIdx.x;
    const float* p = in + (size_t)row * in_stride;
    float ss = 0.f;
    for (int c = threadIdx.x; c < C; c += 256) { float v = p[c]; ss = fmaf(v, v, ss); }
    __shared__ float red[8];
    #pragma unroll
    for (int off = 16; off; off >>= 1) ss += __shfl_xor_sync(0xffffffffu, ss, off);
    if ((threadIdx.x & 31) == 0) red[threadIdx.x >> 5] = ss;
    __syncthreads();
    if (threadIdx.x < 8) {
        float v = red[threadIdx.x];
        #pragma unroll
        for (int off = 4; off; off >>= 1) v += __shfl_xor_sync(0xffu, v, off);
        if (threadIdx.x == 0) red[0] = v;
    }
    __syncthreads();
    const float inv = rsqrtf(red[0] / (float)C + 1e-6f);
    for (int c = threadIdx.x; c < C; c += 256) {
        float v = p[c] * inv * scale[c];
        __nv_bfloat16 h, l; split_bf16(v, h, l);
        size_t o = (size_t)row * C + c;
        oh[o] = h; ol[o] = l;
    }
}

// -------------- fused RoPE + per-head split pre-passes ----------------------
__device__ __forceinline__ float rope_elem(const float* base, int e, float pos) {
    const int j = e & 31;
    const float inv_freq = exp2f(-(float)j * (13.287712379549449f / 32.f));
    float s, c;
    sincosf(pos * inv_freq, &s, &c);
    return (e < 32) ? base[e] * c - base[e + 32] * s
                    : base[e] * c + base[e - 32] * s;
}

// Q rot section: reads compact g_qrot [bht][64], writes Q dims 128..191
__global__ __launch_bounds__(256) void qrot_split_kernel(
    const float* __restrict__ qrot, const int* __restrict__ positions,
    __nv_bfloat16* __restrict__ Qh, __nv_bfloat16* __restrict__ Ql)
{
    const size_t total = (size_t)B_ * NH_ * T_ * (DR_ / 2);
    size_t idx = (size_t)blockIdx.x * 256 + threadIdx.x;
    if (idx >= total) return;
    const int dp = idx % (DR_ / 2);
    const size_t bht = idx / (DR_ / 2);
    const int t = bht % T_;
    const int b = (bht / T_) >> 4;
    const float* rot = qrot + bht * DR_;
    const float pos = (float)positions[b * T_ + t];
    const int e0 = 2 * dp;
    const float v0 = rope_elem(rot, e0, pos);
    const float v1 = rope_elem(rot, e0 + 1, pos);
    const size_t o = bht * DQK_ + DN_ + e0;
    *reinterpret_cast<__nv_bfloat162*>(&Qh[o]) = split2_h(v0, v1);
    *reinterpret_cast<__nv_bfloat162*>(&Ql[o]) = split2_l(v0, v1);
}

// K rot section: dims 128..191, roped ckv columns (shared across heads)
__global__ __launch_bounds__(256) void krot_split_kernel(
    const float* __restrict__ qa2, const int* __restrict__ positions,
    __nv_bfloat16* __restrict__ Kh, __nv_bfloat16* __restrict__ Kl)
{
    const size_t total = (size_t)B_ * NH_ * T_ * (DR_ / 2);
    size_t idx = (size_t)blockIdx.x * 256 + threadIdx.x;
    if (idx >= total) return;
    const int dp = idx % (DR_ / 2);
    const size_t bht = idx / (DR_ / 2);
    const int t = bht % T_;
    const int b = (bht / T_) >> 4;
    const float* rot = qa2 + ((size_t)(b * T_ + t)) * QAW_ + QLR_ + KVLR_;
    const float pos = (float)positions[b * T_ + t];
    const int e0 = 2 * dp;
    const float v0 = rope_elem(rot, e0, pos);
    const float v1 = rope_elem(rot, e0 + 1, pos);
    const size_t o = bht * DQK_ + DN_ + e0;
    *reinterpret_cast<__nv_bfloat162*>(&Kh[o]) = split2_h(v0, v1);
    *reinterpret_cast<__nv_bfloat162*>(&Kl[o]) = split2_l(v0, v1);
}

// ------------------- tensor-core flash attention (split bf16) ---------------
#define QSTR 400
#define VSTR 272
#define SQH  0
#define SSTG (128 * QSTR)
#define STG_KL 25600
#define STG_VH 51200
#define STG_VL 68608
#define STG_SZ 86016
#define ASMEM (SSTG + 2 * STG_SZ)   // 223232

__global__ __launch_bounds__(256) void attn_mma_kernel(
    const __nv_bfloat16* __restrict__ Qh, const __nv_bfloat16* __restrict__ Ql,
    const __nv_bfloat16* __restrict__ Kh, const __nv_bfloat16* __restrict__ Kl,
    const __nv_bfloat16* __restrict__ Vh, const __nv_bfloat16* __restrict__ Vl,
    __nv_bfloat16* __restrict__ oh, __nv_bfloat16* __restrict__ ol)
{
    extern __shared__ char smem[];
    const uint32_t sbase = smem_u32(smem);
    const int tid = threadIdx.x, warp = tid >> 5, lane = tid & 31;
    const int qblk = gridDim.x - 1 - blockIdx.x;
    const int h = blockIdx.y, b = blockIdx.z;
    const int q0 = qblk * 128;
    const int bh = b * NH_ + h;

    const int arow = warp * 16 + (lane & 15);
    const int akof = (lane >> 4) * 8;
    const int brow = (lane >> 4) * 8 + (lane & 7);
    const int bkof = ((lane >> 3) & 1) * 8;
    const int vkof = ((lane >> 3) & 1) * 8 + (lane & 7);
    const int vnof = (lane >> 4) * 8;

    const size_t qoff = ((size_t)bh * T_ + q0) * DQK_;
    for (int i = tid; i < 128 * 24; i += 256) {
        const int r = i / 24, c = i % 24;
        cp16(sbase + SSTG + r * QSTR + c * 16, Ql + qoff + (size_t)r * DQK_ + c * 8, true);
    }
    CP_COMMIT(); CP_WAIT(0);
    __syncthreads();
    uint32_t ql[12][4];
    #pragma unroll
    for (int ks = 0; ks < 12; ks++)
        ldm_x4(ql[ks], sbase + SSTG + arow * QSTR + (ks * 16 + akof) * 2);
    __syncthreads();

    auto load_kv = [&](int ch, int s) {
        const int kk0 = ch * 64;
        const size_t koff = ((size_t)bh * T_ + kk0) * DQK_;
        const size_t voff = ((size_t)bh * T_ + kk0) * DV_;
        const uint32_t stg = sbase + SSTG + (uint32_t)s * STG_SZ;
        for (int i = tid; i < 64 * 24; i += 256) {
            const int r = i / 24, c = i % 24;
            cp16(stg + r * QSTR + c * 16, Kh + koff + (size_t)r * DQK_ + c * 8, true);
            cp16(stg + STG_KL + r * QSTR + c * 16, Kl + koff + (size_t)r * DQK_ + c * 8, true);
        }
        for (int i = tid; i < 64 * 16; i += 256) {
            const int r = i >> 4, c = i & 15;
            cp16(stg + STG_VH + r * VSTR + c * 16, Vh + voff + (size_t)r * DV_ + c * 8, true);
            cp16(stg + STG_VL + r * VSTR + c * 16, Vl + voff + (size_t)r * DV_ + c * 8, true);
        }
    };

    for (int i = tid; i < 128 * 24; i += 256) {
        const int r = i / 24, c = i % 24;
        cp16(sbase + SQH + r * QSTR + c * 16, Qh + qoff + (size_t)r * DQK_ + c * 8, true);
    }
    load_kv(0, 0);
    CP_COMMIT();

    float S[8][4], O[16][4];
    #pragma unroll
    for (int t = 0; t < 16; t++)
        #pragma unroll
        for (int e = 0; e < 4; e++) O[t][e] = 0.f;
    float m0 = -1e30f, m1 = -1e30f, l0 = 0.f, l1 = 0.f;
    const float scale = 0.07216878364870323f;  // 192^-0.5

    const int r0g = q0 + warp * 16 + (lane >> 2);
    const int r1g = r0g + 8;
    const int wrow_max = q0 + warp * 16 + 15;

    const int nch = 2 * qblk + 2;
    for (int ch = 0; ch < nch; ch++) {
        const int k0 = ch * 64;
        if (ch + 1 < nch) { load_kv(ch + 1, (ch + 1) & 1); CP_COMMIT(); CP_WAIT(1); }
        else              { CP_WAIT(0); }
        __syncthreads();

        const bool active = (k0 <= wrow_max);
        if (active) {
            const uint32_t stg = sbase + SSTG + (uint32_t)(ch & 1) * STG_SZ;

            #pragma unroll
            for (int t = 0; t < 8; t++)
                #pragma unroll
                for (int e = 0; e < 4; e++) S[t][e] = 0.f;
            #pragma unroll
            for (int ks = 0; ks < 12; ks++) {
                uint32_t ah4[4];
                ldm_x4(ah4, sbase + SQH + arow * QSTR + (ks * 16 + akof) * 2);
                #pragma unroll
                for (int p = 0; p < 4; p++) {
                    uint32_t rh[4], rl[4];
                    const uint32_t bd = stg + (p * 16 + brow) * QSTR
                                        + (ks * 16 + bkof) * 2;
                    ldm_x4(rh, bd);
                    ldm_x4(rl, bd + STG_KL);
                    mma16816(S[2*p],   ah4, rh);
                    mma16816(S[2*p],   ah4, rl);
                    mma16816(S[2*p],   ql[ks], rh);
                    mma16816(S[2*p+1], ah4, rh + 2);
                    mma16816(S[2*p+1], ah4, rl + 2);
                    mma16816(S[2*p+1], ql[ks], rh + 2);
                }
            }

            const bool dm = (k0 + 63 > q0);
            #pragma unroll
            for (int t = 0; t < 8; t++) {
                #pragma unroll
                for (int e = 0; e < 4; e++) {
                    float v = S[t][e] * scale;
                    if (dm) {
                        const int kg = k0 + t * 8 + (lane & 3) * 2 + (e & 1);
                        const int rg = (e < 2) ? r0g : r1g;
                        if (kg > rg) v = -1e30f;
                    }
                    S[t][e] = v;
                }
            }

            float mx0 = -1e30f, mx1 = -1e30f;
            #pragma unroll
            for (int t = 0; t < 8; t++) {
                mx0 = fmaxf(mx0, fmaxf(S[t][0], S[t][1]));
                mx1 = fmaxf(mx1, fmaxf(S[t][2], S[t][3]));
            }
            mx0 = fmaxf(mx0, __shfl_xor_sync(0xffffffffu, mx0, 1));
            mx0 = fmaxf(mx0, __shfl_xor_sync(0xffffffffu, mx0, 2));
            mx1 = fmaxf(mx1, __shfl_xor_sync(0xffffffffu, mx1, 1));
            mx1 = fmaxf(mx1, __shfl_xor_sync(0xffffffffu, mx1, 2));
            const float mn0 = fmaxf(m0, mx0), mn1 = fmaxf(m1, mx1);
            const float a0 = __expf(m0 - mn0), a1 = __expf(m1 - mn1);
            float s0 = 0.f, s1 = 0.f;
            #pragma unroll
            for (int t = 0; t < 8; t++) {
                S[t][0] = __expf(S[t][0] - mn0); s0 += S[t][0];
                S[t][1] = __expf(S[t][1] - mn0); s0 += S[t][1];
                S[t][2] = __expf(S[t][2] - mn1); s1 += S[t][2];
                S[t][3] = __expf(S[t][3] - mn1); s1 += S[t][3];
            }
            s0 += __shfl_xor_sync(0xffffffffu, s0, 1);
            s0 += __shfl_xor_sync(0xffffffffu, s0, 2);
            s1 += __shfl_xor_sync(0xffffffffu, s1, 1);
            s1 += __shfl_xor_sync(0xffffffffu, s1, 2);
            l0 = l0 * a0 + s0;  l1 = l1 * a1 + s1;
            m0 = mn0;  m1 = mn1;
            #pragma unroll
            for (int t = 0; t < 16; t++) {
                O[t][0] *= a0; O[t][1] *= a0; O[t][2] *= a1; O[t][3] *= a1;
            }

            #pragma unroll
            for (int kt = 0; kt < 4; kt++) {
                uint32_t pah[4], pal[4];
                #pragma unroll
                for (int i = 0; i < 4; i++) {
                    const float p0 = S[2*kt + (i >> 1)][(i & 1) * 2];
                    const float p1 = S[2*kt + (i >> 1)][(i & 1) * 2 + 1];
                    __nv_bfloat162 hh = split2_h(p0, p1);
                    __nv_bfloat162 ll = split2_l(p0, p1);
                    pah[i] = *reinterpret_cast<uint32_t*>(&hh);
                    pal[i] = *reinterpret_cast<uint32_t*>(&ll);
                }
                #pragma unroll
                for (int vt = 0; vt < 8; vt++) {
                    uint32_t rh[4], rl[4];
                    const uint32_t vd = stg + STG_VH + (kt * 16 + vkof) * VSTR
                                        + (vt * 16 + vnof) * 2;
                    ldm_x4_t(rh, vd);
                    ldm_x4_t(rl, vd + (STG_VL - STG_VH));
                    mma16816(O[2*vt],   pah, rh);
                    mma16816(O[2*vt],   pah, rl);
                    mma16816(O[2*vt],   pal, rh);
                    mma16816(O[2*vt+1], pah, rh + 2);
                    mma16816(O[2*vt+1], pah, rl + 2);
                    mma16816(O[2*vt+1], pal, rh + 2);
                }
            }
        }
        __syncthreads();
    }

    const float i0 = 1.f / l0, i1 = 1.f / l1;
    const size_t obase0 = ((size_t)(b * T_ + r0g)) * (NH_ * DV_) + h * DV_;
    const size_t obase1 = ((size_t)(b * T_ + r1g)) * (NH_ * DV_) + h * DV_;
    #pragma unroll
    for (int t = 0; t < 16; t++) {
        const int d = t * 8 + (lane & 3) * 2;
        *reinterpret_cast<__nv_bfloat162*>(&oh[obase0 + d]) =
            split2_h(O[t][0] * i0, O[t][1] * i0);
        *reinterpret_cast<__nv_bfloat162*>(&ol[obase0 + d]) =
            split2_l(O[t][0] * i0, O[t][1] * i0);
        *reinterpret_cast<__nv_bfloat162*>(&oh[obase1 + d]) =
            split2_h(O[t][2] * i1, O[t][3] * i1);
        *reinterpret_cast<__nv_bfloat162*>(&ol[obase1 + d]) =
            split2_l(O[t][2] * i1, O[t][3] * i1);
    }
}

// ------------------------------- launcher -----------------------------------
static inline void run_gemm(const __nv_bfloat16* Ah, const __nv_bfloat16* Al,
                            const __nv_bfloat16* Bh, const __nv_bfloat16* Bl,
                            float* C, int M, int N, int K)
{
    dim3 grid((N + 127) / 128, M / 128);
    gemm_mma_f32<<<grid, 256, GSMEM>>>(Ah, Al, Bh, Bl, C, M, N, K);
}

extern "C" void kernel_launch(void* const* d_in, const int* in_sizes, int n_in,
                              void* d_out, int out_size)
{
    const float* x         = (const float*)d_in[0];
    const int*   positions = (const int*)  d_in[2];
    const float* wqa       = (const float*)d_in[3];
    const float* qa_scale  = (const float*)d_in[4];
    const float* wqb       = (const float*)d_in[5];
    const float* wkva      = (const float*)d_in[6];
    const float* kva_scale = (const float*)d_in[7];
    const float* wkvb      = (const float*)d_in[8];
    const float* wo        = (const float*)d_in[9];
    float* out = (float*)d_out;

    cudaFuncSetAttribute(gemm_mma_f32,
                         cudaFuncAttributeMaxDynamicSharedMemorySize, GSMEM);
    cudaFuncSetAttribute(gemm_mma_qkv,
                         cudaFuncAttributeMaxDynamicSharedMemorySize, GSMEM);
    cudaFuncSetAttribute(attn_mma_kernel,
                         cudaFuncAttributeMaxDynamicSharedMemorySize, ASMEM);

    float *qa2, *qrot;
    cudaGetSymbolAddress((void**)&qa2,  g_qa2);
    cudaGetSymbolAddress((void**)&qrot, g_qrot);
    __nv_bfloat16 *xh, *xl, *qanh, *qanl, *kvnh, *kvnl, *ath, *atl;
    __nv_bfloat16 *wqkvah, *wqkval, *wqbh, *wqbl, *wkvbh, *wkvbl, *woh, *wol;
    __nv_bfloat16 *Qh, *Ql, *Kh, *Kl, *Vh, *Vl;
    cudaGetSymbolAddress((void**)&xh,   g_x_h);   cudaGetSymbolAddress((void**)&xl,   g_x_l);
    cudaGetSymbolAddress((void**)&qanh, g_qan_h); cudaGetSymbolAddress((void**)&qanl, g_qan_l);
    cudaGetSymbolAddress((void**)&kvnh, g_kvn_h); cudaGetSymbolAddress((void**)&kvnl, g_kvn_l);
    cudaGetSymbolAddress((void**)&ath,  g_att_h); cudaGetSymbolAddress((void**)&atl,  g_att_l);
    cudaGetSymbolAddress((void**)&wqkvah, g_wqkva_h);
    cudaGetSymbolAddress((void**)&wqkval, g_wqkva_l);
    cudaGetSymbolAddress((void**)&wqbh, g_wqb_h); cudaGetSymbolAddress((void**)&wqbl, g_wqb_l);
    cudaGetSymbolAddress((void**)&wkvbh, g_wkvb_h); cudaGetSymbolAddress((void**)&wkvbl, g_wkvb_l);
    cudaGetSymbolAddress((void**)&woh,  g_wo_h);  cudaGetSymbolAddress((void**)&wol,  g_wo_l);
    cudaGetSymbolAddress((void**)&Qh, g_Qh); cudaGetSymbolAddress((void**)&Ql, g_Ql);
    cudaGetSymbolAddress((void**)&Kh, g_Kh); cudaGetSymbolAddress((void**)&Kl, g_Kl);
    cudaGetSymbolAddress((void**)&Vh, g_Vh); cudaGetSymbolAddress((void**)&Vl, g_Vl);

    // 0. split x; transpose+split weights
    {
        size_t n = (size_t)ROWS_ * HID_;
        split_kernel<<<(unsigned)((n + 255) / 256), 256>>>(x, xh, xl, n);
        tsplit_kernel<<<dim3(QLR_/32, HID_/32), 256>>>(wqa, wqkvah, wqkval, HID_, QLR_);
        tsplit_kernel<<<dim3(CKVW_/32, HID_/32), 256>>>(
            wkva, wqkvah + (size_t)QLR_ * HID_, wqkval + (size_t)QLR_ * HID_, HID_, CKVW_);
        tsplit_kernel<<<dim3(QW_/32, QLR_/32), 256>>>(wqb, wqbh, wqbl, QLR_, QW_);
        tsplit_kernel<<<dim3(KVW_/32, KVLR_/32), 256>>>(wkvb, wkvbh, wkvbl, KVLR_, KVW_);
        tsplit_kernel<<<dim3(HID_/32, (NH_*DV_)/32), 256>>>(wo, woh, wol, NH_*DV_, HID_);
    }
    // 1. merged [qa | ckv] = x @ [wqa | wkva]
    run_gemm(xh, xl, wqkvah, wqkval, qa2, ROWS_, QAW_, HID_);
    // 2. both rmsnorms (independent)
    rmsnorm_split_kernel<<<ROWS_, 256>>>(qa2, QAW_, qa_scale, qanh, qanl, QLR_);
    rmsnorm_split_kernel<<<ROWS_, 256>>>(qa2 + QLR_, QAW_, kva_scale, kvnh, kvnl, KVLR_);
    // 3. merged q + kv projection GEMM (z=0: q/EPI2, z=1: kv/EPI1)
    {
        dim3 grid(KVW_ / 128, ROWS_ / 128, 2);
        gemm_mma_qkv<<<grid, 256, GSMEM>>>(
            qanh, qanl, wqbh, wqbl,
            kvnh, kvnl, wkvbh, wkvbl,
            qrot, Qh, Ql, Kh, Kl, Vh, Vl);
    }
    // 4. rot-only rope + split for Q and K
    {
        size_t nr = (size_t)B_ * NH_ * T_ * (DR_ / 2);
        qrot_split_kernel<<<(unsigned)((nr + 255) / 256), 256>>>(qrot, positions, Qh, Ql);
        krot_split_kernel<<<(unsigned)((nr + 255) / 256), 256>>>(qa2, positions, Kh, Kl);
    }
    // 5. tensor-core flash attention
    {
        dim3 grid(T_ / 128, NH_, B_);
        attn_mma_kernel<<<grid, 256, ASMEM>>>(Qh, Ql, Kh, Kl, Vh, Vl, ath, atl);
    }
    // 6. out = attn @ wo
    run_gemm(ath, atl, woh, wol, out, ROWS_, HID_, NH_ * DV_);
}